// round 10
// baseline (speedup 1.0000x reference)
#include <cuda_runtime.h>
#include <cuda_bf16.h>
#include <cstdint>

typedef unsigned int uint;

#define C_IN    64
#define INHW    224
#define C_OUT   128
#define OHW     222
#define NPIX    (OHW*OHW)          // 49284
#define NTAP    9
#define TILE_N  128
#define NTILES  ((NPIX + TILE_N - 1)/TILE_N)   // 386

// x transposed to [h][w][ic] bf16, split hi/lo (6.4 MB each)
__device__ __align__(16) __nv_bfloat16 g_xhi[INHW*INHW*C_IN];
__device__ __align__(16) __nv_bfloat16 g_xlo[INHW*INHW*C_IN];
// w rearranged to [tap][oc][ic] bf16, split hi/lo (144 KB each)
__device__ __align__(16) __nv_bfloat16 g_whi[NTAP*C_OUT*C_IN];
__device__ __align__(16) __nv_bfloat16 g_wlo[NTAP*C_OUT*C_IN];

// ---------------- prep kernels ----------------
__global__ void prep_x_kernel(const float* __restrict__ x) {
    int i = blockIdx.x * 256 + threadIdx.x;      // INHW*INHW*8 threads
    if (i >= INHW*INHW*8) return;
    int hw = i >> 3;
    int g  = i & 7;                               // ic group of 8
    __align__(16) __nv_bfloat16 hi[8];
    __align__(16) __nv_bfloat16 lo[8];
    #pragma unroll
    for (int q = 0; q < 8; ++q) {
        float v = x[(size_t)(g*8 + q) * (INHW*INHW) + hw];
        __nv_bfloat16 h = __float2bfloat16(v);
        hi[q] = h;
        lo[q] = __float2bfloat16(v - __bfloat162float(h));
    }
    *(uint4*)&g_xhi[(size_t)hw*64 + g*8] = *(const uint4*)hi;
    *(uint4*)&g_xlo[(size_t)hw*64 + g*8] = *(const uint4*)lo;
}

__global__ void prep_w_kernel(const float* __restrict__ w) {
    int i = blockIdx.x * 256 + threadIdx.x;      // 9*128*64 = 73728
    if (i >= NTAP*C_OUT*C_IN) return;
    int ic = i & 63;
    int r  = i >> 6;
    int oc = r & 127;
    int t  = r >> 7;
    float v = w[(size_t)(oc*C_IN + ic)*NTAP + t];
    __nv_bfloat16 h = __float2bfloat16(v);
    g_whi[i] = h;
    g_wlo[i] = __float2bfloat16(v - __bfloat162float(h));
}

// ---------------- PTX helpers (all sm_80-era, compute_103-safe) ----------------
__device__ __forceinline__ uint smem_u32(const void* p) {
    uint a;
    asm("{ .reg .u64 t; cvta.to.shared.u64 t, %1; cvt.u32.u64 %0, t; }"
        : "=r"(a) : "l"(p));
    return a;
}
__device__ __forceinline__ void cpa16(uint d, const void* s) {
    asm volatile("cp.async.ca.shared.global [%0], [%1], 16;" :: "r"(d), "l"(s) : "memory");
}
__device__ __forceinline__ void cpa_commit() {
    asm volatile("cp.async.commit_group;" ::: "memory");
}
__device__ __forceinline__ void cpa_wait1() {
    asm volatile("cp.async.wait_group 1;" ::: "memory");
}
__device__ __forceinline__ void cpa_wait0() {
    asm volatile("cp.async.wait_group 0;" ::: "memory");
}
__device__ __forceinline__ void ldsm4(uint& r0, uint& r1, uint& r2, uint& r3, uint a) {
    asm volatile("ldmatrix.sync.aligned.m8n8.x4.shared.b16 {%0,%1,%2,%3}, [%4];"
                 : "=r"(r0), "=r"(r1), "=r"(r2), "=r"(r3) : "r"(a));
}
__device__ __forceinline__ void mma_bf16(float* c, const uint* a, uint b0, uint b1) {
    asm volatile("mma.sync.aligned.m16n8k16.row.col.f32.bf16.bf16.f32 "
                 "{%0,%1,%2,%3}, {%4,%5,%6,%7}, {%8,%9}, {%0,%1,%2,%3};"
                 : "+f"(c[0]), "+f"(c[1]), "+f"(c[2]), "+f"(c[3])
                 : "r"(a[0]), "r"(a[1]), "r"(a[2]), "r"(a[3]), "r"(b0), "r"(b1));
}

// ---------------- SMEM layout: TWO full 64 KB tap buffers (occ 1) ----------------
#define SM_A_HI   0
#define SM_A_LO   16384
#define SM_B_HI   32768
#define SM_B_LO   49152
#define BUF_SZ    65536
#define SMEM_SZ   (2*BUF_SZ)       // 131072

// ---------------- main kernel ----------------
__global__ __launch_bounds__(256, 1)
void conv_hmma_db_kernel(float* __restrict__ out)
{
    extern __shared__ char smem[];
    const uint sb  = smem_u32(smem);
    const int tid  = threadIdx.x;
    const int wid  = tid >> 5;
    const int lid  = tid & 31;
    const int wm   = wid & 1;          // m-half (64 rows)
    const int wn   = wid >> 1;         // n-quarter (32 cols)

    const size_t p0 = (size_t)blockIdx.x * TILE_N;

    // ---- staging assignment (tid<128: A row 'tid'; tid>=128: B row 'tid-128') ----
    const int srow  = tid & 127;
    const int rowsw = srow & 7;                 // swizzle key for this staged row
    const char* srcH;
    const char* srcL;
    if (tid < 128) {
        srcH = (const char*)g_whi + (size_t)srow * 128;
        srcL = (const char*)g_wlo + (size_t)srow * 128;
    } else {
        size_t p = p0 + srow; if (p >= NPIX) p = NPIX - 1;   // masked at store
        const int boh = (int)(p / OHW), bow = (int)(p - (size_t)boh * OHW);
        srcH = (const char*)g_xhi + ((size_t)boh * INHW + bow) * 128;
        srcL = (const char*)g_xlo + ((size_t)boh * INHW + bow) * 128;
    }
    const uint dH0 = sb + (tid < 128 ? SM_A_HI : SM_B_HI) + (uint)srow * 128;
    const uint dL0 = sb + (tid < 128 ? SM_A_LO : SM_B_LO) + (uint)srow * 128;
    const bool isA = (tid < 128);

    // ---- ldmatrix per-lane base offsets (within a buffer) ----
    const int  rA = wm * 64 + (lid & 15);
    const int  sA = lid >> 4;
    const uint aHoff = SM_A_HI + (uint)rA * 128;
    const uint aLoff = SM_A_LO + (uint)rA * 128;
    const int  rB = wn * 32 + ((lid >> 4) << 3) + (lid & 7);
    const int  sB = (lid >> 3) & 1;
    const uint bHoff = SM_B_HI + (uint)rB * 128;
    const uint bLoff = SM_B_LO + (uint)rB * 128;
    const int  cA = rA & 7;
    const int  cB = rB & 7;

    float acc[64];
    #pragma unroll
    for (int i = 0; i < 64; ++i) acc[i] = 0.f;

    // ---- stage one full tap (16 cp.async.16 per thread) into buffer (t&1) ----
    auto stage = [&](int t) {
        const int kr = t / 3, ks = t - kr * 3;
        const size_t off = isA ? (size_t)t * ((size_t)C_OUT * 128)
                               : (size_t)(kr * INHW + ks) * 128;
        const uint bo = (uint)(t & 1) * BUF_SZ;
        #pragma unroll
        for (int j = 0; j < 8; ++j) {
            const uint sw = (uint)((j ^ rowsw) << 4);
            cpa16(dH0 + bo + sw, srcH + off + j * 16);
            cpa16(dL0 + bo + sw, srcL + off + j * 16);
        }
    };

    // prologue: taps 0 and 1 in flight
    stage(0); cpa_commit();
    stage(1); cpa_commit();

    #pragma unroll 1
    for (int t = 0; t < NTAP; ++t) {
        if (t < NTAP - 1) cpa_wait1();   // tap t complete (t+1 may be in flight)
        else              cpa_wait0();
        __syncthreads();                 // tap t visible to all warps

        // ---- compute tap t from buffer (t&1): 4 k16-steps, 3 passes fused ----
        const uint bo = (uint)(t & 1) * BUF_SZ;
        const uint aHbase = sb + bo + aHoff;
        const uint aLbase = sb + bo + aLoff;
        const uint bHbase = sb + bo + bHoff;
        const uint bLbase = sb + bo + bLoff;
        #pragma unroll
        for (int k = 0; k < 4; ++k) {
            uint bhi[8], blo[8];
            #pragma unroll
            for (int q = 0; q < 2; ++q) {
                const uint segoff = (uint)(((2 * k + sB) ^ cB) << 4) + (uint)q * 2048;
                ldsm4(bhi[q*4+0], bhi[q*4+1], bhi[q*4+2], bhi[q*4+3], bHbase + segoff);
                ldsm4(blo[q*4+0], blo[q*4+1], blo[q*4+2], blo[q*4+3], bLbase + segoff);
            }
            #pragma unroll
            for (int i = 0; i < 4; ++i) {
                const uint segA = (uint)(((2 * k + sA) ^ cA) << 4) + (uint)i * 2048;
                uint ahi[4], alo[4];
                ldsm4(ahi[0], ahi[1], ahi[2], ahi[3], aHbase + segA);
                ldsm4(alo[0], alo[1], alo[2], alo[3], aLbase + segA);
                #pragma unroll
                for (int j = 0; j < 4; ++j) {
                    float* cacc = &acc[(i * 4 + j) * 4];
                    mma_bf16(cacc, ahi, bhi[j*2], bhi[j*2+1]);   // Whi*Xhi
                    mma_bf16(cacc, ahi, blo[j*2], blo[j*2+1]);   // Whi*Xlo
                    mma_bf16(cacc, alo, bhi[j*2], bhi[j*2+1]);   // Wlo*Xhi
                }
            }
        }
        __syncthreads();                 // all reads of buffer (t&1) done

        if (t + 2 < NTAP) {              // refill the buffer just freed
            stage(t + 2);
            cpa_commit();
        }
    }

    // ---- epilogue ----
    const int ml = wm * 64 + (lid >> 2);
    const int nl = wn * 32 + (lid & 3) * 2;
    #pragma unroll
    for (int i = 0; i < 4; ++i) {
        #pragma unroll
        for (int j = 0; j < 4; ++j) {
            const float* c = &acc[(i * 4 + j) * 4];
            const int n = nl + j * 8;
            const size_t p = p0 + n;
            if (p < NPIX) {                       // NPIX%4==0 -> pair fully valid
                const int m0 = ml + i * 16;
                *(float2*)(out + (size_t)m0 * NPIX + p)       = make_float2(c[0], c[1]);
                *(float2*)(out + (size_t)(m0 + 8) * NPIX + p) = make_float2(c[2], c[3]);
            }
        }
    }
}

// ---------------- launch ----------------
extern "C" void kernel_launch(void* const* d_in, const int* in_sizes, int n_in,
                              void* d_out, int out_size)
{
    const float* x = (const float*)d_in[0];   // (64, 224, 224) f32
    const float* w = (const float*)d_in[1];   // (128, 64, 3, 3) f32
    float* out = (float*)d_out;               // (128, 222, 222) f32

    cudaFuncSetAttribute(conv_hmma_db_kernel,
                         cudaFuncAttributeMaxDynamicSharedMemorySize, SMEM_SZ);

    prep_x_kernel<<<(INHW*INHW*8 + 255) / 256, 256>>>(x);
    prep_w_kernel<<<(NTAP*C_OUT*C_IN + 255) / 256, 256>>>(w);
    conv_hmma_db_kernel<<<NTILES, 256, SMEM_SZ>>>(out);
}

// round 11
// speedup vs baseline: 3.4370x; 3.4370x over previous
#include <cuda_runtime.h>
#include <cuda_fp16.h>
#include <cstdint>

typedef unsigned int uint;

#define C_IN    64
#define INHW    224
#define NQ      (INHW*INHW)        // 50176 input pixels
#define QMAX    (NQ-1)
#define C_OUT   128
#define OHW     222
#define NPIX    (OHW*OHW)          // 49284
#define NTAP    9
#define TILE_N  128
#define NTILES  ((NPIX + TILE_N - 1)/TILE_N)   // 386
#define BROWS   132                // B smem rows per kr (128 + ks 2 + rowcross 2)

// x transposed to [q][ic] fp16 (6.4 MB), linear (swizzle applied at LDGSTS time)
__device__ __align__(16) __half g_xf[NQ * C_IN];
// w as [tap][oc][ic] fp16 with XOR-swizzle pre-baked per oc row (for verbatim bulk copy)
__device__ __align__(16) __half g_wf[NTAP * C_OUT * C_IN];

// ---------------- prep kernels ----------------
__global__ void prep_x_kernel(const float* __restrict__ x) {
    int i = blockIdx.x * 256 + threadIdx.x;      // NQ*8 threads
    if (i >= NQ * 8) return;
    int q = i >> 3;
    int g = i & 7;                                // ic granule (8 ch)
    __align__(16) __half h[8];
    #pragma unroll
    for (int c = 0; c < 8; ++c)
        h[c] = __float2half(x[(size_t)(g * 8 + c) * NQ + q]);
    *(uint4*)&g_xf[(size_t)q * 64 + g * 8] = *(const uint4*)h;
}

__global__ void prep_w_kernel(const float* __restrict__ w) {
    int i = blockIdx.x * 256 + threadIdx.x;      // 9*128*64 = 73728
    if (i >= NTAP * C_OUT * C_IN) return;
    int ic = i & 63;
    int r  = i >> 6;
    int oc = r & 127;
    int t  = r >> 7;
    // source w[oc][ic][t]
    float v = w[(size_t)(oc * C_IN + ic) * NTAP + t];
    // dest: tap slab t, row oc, 16B granule j=ic>>3 stored at position j^(oc&7)
    int j  = ic >> 3;
    int jp = j ^ (oc & 7);
    g_wf[(size_t)t * (C_OUT * C_IN) + oc * C_IN + jp * 8 + (ic & 7)] = __float2half(v);
}

// ---------------- PTX helpers (sm_90-baseline, compute_103-safe) ----------------
__device__ __forceinline__ uint smem_u32(const void* p) {
    uint a;
    asm("{ .reg .u64 t; cvta.to.shared.u64 t, %1; cvt.u32.u64 %0, t; }"
        : "=r"(a) : "l"(p));
    return a;
}
__device__ __forceinline__ void cpa16(uint d, const void* s) {
    asm volatile("cp.async.ca.shared.global [%0], [%1], 16;" :: "r"(d), "l"(s) : "memory");
}
__device__ __forceinline__ void cpa_commit() {
    asm volatile("cp.async.commit_group;" ::: "memory");
}
__device__ __forceinline__ void cpa_wait1() {
    asm volatile("cp.async.wait_group 1;" ::: "memory");
}
__device__ __forceinline__ void cpa_wait0() {
    asm volatile("cp.async.wait_group 0;" ::: "memory");
}
__device__ __forceinline__ void mbar_init(uint a, uint cnt) {
    asm volatile("mbarrier.init.shared.b64 [%0], %1;" :: "r"(a), "r"(cnt) : "memory");
}
__device__ __forceinline__ void mbar_expect_tx(uint a, uint bytes) {
    asm volatile("mbarrier.arrive.expect_tx.shared.b64 _, [%0], %1;"
                 :: "r"(a), "r"(bytes) : "memory");
}
__device__ __forceinline__ void bulk_g2s(uint dst, const void* src, uint bytes, uint mbar) {
    asm volatile("cp.async.bulk.shared::cluster.global.mbarrier::complete_tx::bytes "
                 "[%0], [%1], %2, [%3];"
                 :: "r"(dst), "l"(src), "r"(bytes), "r"(mbar) : "memory");
}
__device__ __forceinline__ void fence_async() {
    asm volatile("fence.proxy.async.shared::cta;" ::: "memory");
}
__device__ __forceinline__ void mbar_wait(uint a, uint parity) {
    uint done;
    asm volatile("{\n\t.reg .pred p;\n\t"
                 "mbarrier.try_wait.parity.acquire.cta.shared::cta.b64 p, [%1], %2;\n\t"
                 "selp.b32 %0, 1, 0, p;\n\t}"
                 : "=r"(done) : "r"(a), "r"(parity) : "memory");
    if (!done) {
        asm volatile("{\n\t.reg .pred P1;\n\t"
                     "WL_%=:\n\t"
                     "mbarrier.try_wait.parity.acquire.cta.shared::cta.b64 P1, [%0], %1, 0x989680;\n\t"
                     "@P1 bra.uni WD_%=;\n\t"
                     "bra.uni WL_%=;\n\t"
                     "WD_%=:\n\t}"
                     :: "r"(a), "r"(parity) : "memory");
    }
}
__device__ __forceinline__ void ldsm4(uint& r0, uint& r1, uint& r2, uint& r3, uint a) {
    asm volatile("ldmatrix.sync.aligned.m8n8.x4.shared.b16 {%0,%1,%2,%3}, [%4];"
                 : "=r"(r0), "=r"(r1), "=r"(r2), "=r"(r3) : "r"(a));
}
__device__ __forceinline__ void mma_f16(float* c, const uint* a, uint b0, uint b1) {
    asm volatile("mma.sync.aligned.m16n8k16.row.col.f32.f16.f16.f32 "
                 "{%0,%1,%2,%3}, {%4,%5,%6,%7}, {%8,%9}, {%0,%1,%2,%3};"
                 : "+f"(c[0]), "+f"(c[1]), "+f"(c[2]), "+f"(c[3])
                 : "r"(a[0]), "r"(a[1]), "r"(a[2]), "r"(a[3]), "r"(b0), "r"(b1));
}

// ---------------- SMEM layout ----------------
#define SM_MBAR0  0
#define SM_MBAR1  16
#define SM_A0     1024
#define SM_A1     (1024 + 16384)
#define SM_B0     (1024 + 32768)
#define SM_B1     (SM_B0 + BROWS*128)      // +16896
#define SMEM_SZ   (SM_B1 + BROWS*128)      // 67584 -> 2 CTAs/SM

#define A_BYTES   16384

// ---------------- main kernel ----------------
__global__ __launch_bounds__(256, 2)
void conv_hmma_fp16_kernel(float* __restrict__ out)
{
    extern __shared__ char smem[];
    const uint sb  = smem_u32(smem);
    const int tid  = threadIdx.x;
    const int wid  = tid >> 5;
    const int lid  = tid & 31;
    const int wm   = wid & 1;          // m-half (64 rows)
    const int wn   = wid >> 1;         // n-quarter (32 cols)

    const int p0  = blockIdx.x * TILE_N;
    const int oh0 = p0 / OHW;
    const int ow0 = p0 - oh0 * OHW;

    // ---- mbarriers for A bulk copies ----
    if (tid == 0) {
        mbar_init(sb + SM_MBAR0, 1);
        mbar_init(sb + SM_MBAR1, 1);
        fence_async();
    }
    __syncthreads();

    // ---- ldmatrix per-lane constants ----
    const int  rA = wm * 64 + (lid & 15);
    const int  sA = lid >> 4;
    const int  cA = rA & 7;
    const int  rB = wn * 32 + ((lid >> 4) << 3) + (lid & 7);
    const int  sB = (lid >> 3) & 1;
    // per-q B base rows (pixel index within tile + 2 if past output-row boundary)
    int rowQ[2];
    #pragma unroll
    for (int q = 0; q < 2; ++q) {
        const int n = rB + 16 * q;
        rowQ[q] = n + ((ow0 + n >= OHW) ? 2 : 0);
    }

    // ---- B staging (LDGSTS): 132 rows x 8 granules per kr ----
    auto stage_B = [&](int kr) {
        const uint bbuf = sb + ((kr & 1) ? SM_B1 : SM_B0);
        const int  qb   = (oh0 + kr) * INHW + ow0;
        #pragma unroll 1
        for (int idx = tid; idx < BROWS * 8; idx += 256) {
            const int r = idx >> 3;
            const int j = idx & 7;
            const int q = (qb + r) > QMAX ? QMAX : (qb + r);
            cpa16(bbuf + r * 128 + (((j ^ (r & 7))) << 4),
                  (const char*)g_xf + (size_t)q * 128 + j * 16);
        }
    };
    // ---- A staging (single bulk copy, swizzle pre-baked) ----
    auto stage_A = [&](int t) {
        if (tid == 0) {
            const uint mb = sb + ((t & 1) ? SM_MBAR1 : SM_MBAR0);
            mbar_expect_tx(mb, A_BYTES);
            bulk_g2s(sb + ((t & 1) ? SM_A1 : SM_A0),
                     (const char*)g_wf + (size_t)t * A_BYTES, A_BYTES, mb);
        }
    };

    float acc[64];
    #pragma unroll
    for (int i = 0; i < 64; ++i) acc[i] = 0.f;

    // prologue
    stage_B(0); cpa_commit();
    stage_A(0);
    stage_B(1); cpa_commit();
    stage_A(1);

    int phA0 = 0, phA1 = 0;

    #pragma unroll 1
    for (int kr = 0; kr < 3; ++kr) {
        if (kr < 2) cpa_wait1();   // B(kr) done, B(kr+1) may be in flight
        else        cpa_wait0();
        __syncthreads();           // B(kr) visible

        const uint bbuf = sb + ((kr & 1) ? SM_B1 : SM_B0);

        #pragma unroll 1
        for (int ks = 0; ks < 3; ++ks) {
            const int t = kr * 3 + ks;
            const int b = t & 1;
            // wait for A(t)
            if (b == 0) { mbar_wait(sb + SM_MBAR0, phA0); phA0 ^= 1; }
            else        { mbar_wait(sb + SM_MBAR1, phA1); phA1 ^= 1; }

            const uint abuf = sb + (b ? SM_A1 : SM_A0);
            const uint aRow = abuf + (uint)rA * 128;

            #pragma unroll
            for (int k = 0; k < 4; ++k) {
                uint bf[8];
                #pragma unroll
                for (int q = 0; q < 2; ++q) {
                    const int  row  = rowQ[q] + ks;
                    const uint addr = bbuf + (uint)row * 128
                                    + (uint)(((2 * k + sB) ^ (row & 7)) << 4);
                    ldsm4(bf[q*4+0], bf[q*4+1], bf[q*4+2], bf[q*4+3], addr);
                }
                #pragma unroll
                for (int i = 0; i < 4; ++i) {
                    uint a[4];
                    ldsm4(a[0], a[1], a[2], a[3],
                          aRow + (uint)i * 2048 + (uint)(((2 * k + sA) ^ cA) << 4));
                    #pragma unroll
                    for (int j = 0; j < 4; ++j)
                        mma_f16(&acc[(i * 4 + j) * 4], a, bf[j*2], bf[j*2+1]);
                }
            }
            __syncthreads();          // all warps done reading A buffer b (and B on last ks)
            if (t + 2 <= 8) stage_A(t + 2);   // refill freed A buffer
        }
        if (kr == 0) { stage_B(2); cpa_commit(); }   // B buf0 free after kr=0's last sync
    }

    // ---- epilogue (same fragment map as before) ----
    const int ml = wm * 64 + (lid >> 2);
    const int nl = wn * 32 + (lid & 3) * 2;
    #pragma unroll
    for (int i = 0; i < 4; ++i) {
        #pragma unroll
        for (int j = 0; j < 4; ++j) {
            const float* c = &acc[(i * 4 + j) * 4];
            const int n = nl + j * 8;
            const int p = p0 + n;
            if (p < NPIX) {                       // NPIX%4==0 -> pair fully valid
                const int m0 = ml + i * 16;
                *(float2*)(out + (size_t)m0 * NPIX + p)       = make_float2(c[0], c[1]);
                *(float2*)(out + (size_t)(m0 + 8) * NPIX + p) = make_float2(c[2], c[3]);
            }
        }
    }
}

// ---------------- launch ----------------
extern "C" void kernel_launch(void* const* d_in, const int* in_sizes, int n_in,
                              void* d_out, int out_size)
{
    const float* x = (const float*)d_in[0];   // (64, 224, 224) f32
    const float* w = (const float*)d_in[1];   // (128, 64, 3, 3) f32
    float* out = (float*)d_out;               // (128, 222, 222) f32

    cudaFuncSetAttribute(conv_hmma_fp16_kernel,
                         cudaFuncAttributeMaxDynamicSharedMemorySize, SMEM_SZ);

    prep_x_kernel<<<(NQ * 8 + 255) / 256, 256>>>(x);
    prep_w_kernel<<<(NTAP * C_OUT * C_IN + 255) / 256, 256>>>(w);
    conv_hmma_fp16_kernel<<<NTILES, 256, SMEM_SZ>>>(out);
}

// round 12
// speedup vs baseline: 3.5069x; 1.0204x over previous
#include <cuda_runtime.h>
#include <cuda_fp16.h>
#include <cstdint>

typedef unsigned int uint;

#define C_IN    64
#define INHW    224
#define NQ      (INHW*INHW)        // 50176 input pixels
#define QMAX    (NQ-1)
#define C_OUT   128
#define OHW     222
#define NPIX    (OHW*OHW)          // 49284
#define NTAP    9
#define TILE_N  128
#define NTILES  ((NPIX + TILE_N - 1)/TILE_N)   // 386
#define BROWS   132                // B smem rows per kr (128 + ks 2 + rowcross 2)

#define XBLK    (NQ/256)           // 196 transpose blocks
#define WBLK    36                 // 36 blocks x 2048 items = 73728 weight elems

// x transposed to [q][ic] fp16 (6.4 MB), linear (swizzle applied at LDGSTS time)
__device__ __align__(16) __half g_xf[NQ * C_IN];
// w as [tap][oc][ic] fp16 with XOR-swizzle pre-baked per oc row (for verbatim bulk copy)
__device__ __align__(16) __half g_wf[NTAP * C_OUT * C_IN];

// ---------------- combined prep kernel ----------------
// blocks [0, XBLK): coalesced two-stage transpose of x -> g_xf
// blocks [XBLK, XBLK+WBLK): weight conversion -> g_wf
__global__ void prep_kernel(const float* __restrict__ x, const float* __restrict__ w)
{
    const int tid = threadIdx.x;
    if (blockIdx.x < XBLK) {
        __shared__ __half sm[256 * 64];          // 32 KB
        const int q0 = blockIdx.x * 256;
        // phase 1: 64 coalesced channel-row loads; granule-XOR swizzled STS
        #pragma unroll 8
        for (int c = 0; c < 64; ++c) {
            float v = x[(size_t)c * NQ + q0 + tid];
            sm[tid * 64 + (((c >> 3) ^ (tid & 7)) << 3) + (c & 7)] = __float2half(v);
        }
        __syncthreads();
        // phase 2: gather uint4s, coalesced STG.128 to g_xf[q][ic]
        #pragma unroll
        for (int it = 0; it < 8; ++it) {
            const int i = tid + it * 256;        // covers 256 q x 8 granules
            const int q = i >> 3;
            const int g = i & 7;
            uint4 v = *(const uint4*)&sm[q * 64 + ((g ^ (q & 7)) << 3)];
            *(uint4*)&g_xf[(size_t)(q0 + q) * 64 + g * 8] = v;
        }
    } else {
        const int base = (blockIdx.x - XBLK) * 2048 + tid * 8;
        #pragma unroll
        for (int k = 0; k < 8; ++k) {
            const int i = base + k;
            if (i < NTAP * C_OUT * C_IN) {
                const int ic = i & 63;
                const int r  = i >> 6;
                const int oc = r & 127;
                const int t  = r >> 7;
                float v = w[(size_t)(oc * C_IN + ic) * NTAP + t];
                const int jp = (ic >> 3) ^ (oc & 7);
                g_wf[(size_t)t * (C_OUT * C_IN) + oc * C_IN + jp * 8 + (ic & 7)] =
                    __float2half(v);
            }
        }
    }
}

// ---------------- PTX helpers (sm_90-baseline, compute_103-safe) ----------------
__device__ __forceinline__ uint smem_u32(const void* p) {
    uint a;
    asm("{ .reg .u64 t; cvta.to.shared.u64 t, %1; cvt.u32.u64 %0, t; }"
        : "=r"(a) : "l"(p));
    return a;
}
__device__ __forceinline__ void cpa16(uint d, const void* s) {
    asm volatile("cp.async.ca.shared.global [%0], [%1], 16;" :: "r"(d), "l"(s) : "memory");
}
__device__ __forceinline__ void cpa_commit() {
    asm volatile("cp.async.commit_group;" ::: "memory");
}
__device__ __forceinline__ void cpa_wait1() {
    asm volatile("cp.async.wait_group 1;" ::: "memory");
}
__device__ __forceinline__ void cpa_wait0() {
    asm volatile("cp.async.wait_group 0;" ::: "memory");
}
__device__ __forceinline__ void mbar_init(uint a, uint cnt) {
    asm volatile("mbarrier.init.shared.b64 [%0], %1;" :: "r"(a), "r"(cnt) : "memory");
}
__device__ __forceinline__ void mbar_expect_tx(uint a, uint bytes) {
    asm volatile("mbarrier.arrive.expect_tx.shared.b64 _, [%0], %1;"
                 :: "r"(a), "r"(bytes) : "memory");
}
__device__ __forceinline__ void bulk_g2s(uint dst, const void* src, uint bytes, uint mbar) {
    asm volatile("cp.async.bulk.shared::cluster.global.mbarrier::complete_tx::bytes "
                 "[%0], [%1], %2, [%3];"
                 :: "r"(dst), "l"(src), "r"(bytes), "r"(mbar) : "memory");
}
__device__ __forceinline__ void fence_async() {
    asm volatile("fence.proxy.async.shared::cta;" ::: "memory");
}
__device__ __forceinline__ void mbar_wait(uint a, uint parity) {
    uint done;
    asm volatile("{\n\t.reg .pred p;\n\t"
                 "mbarrier.try_wait.parity.acquire.cta.shared::cta.b64 p, [%1], %2;\n\t"
                 "selp.b32 %0, 1, 0, p;\n\t}"
                 : "=r"(done) : "r"(a), "r"(parity) : "memory");
    if (!done) {
        asm volatile("{\n\t.reg .pred P1;\n\t"
                     "WL_%=:\n\t"
                     "mbarrier.try_wait.parity.acquire.cta.shared::cta.b64 P1, [%0], %1, 0x989680;\n\t"
                     "@P1 bra.uni WD_%=;\n\t"
                     "bra.uni WL_%=;\n\t"
                     "WD_%=:\n\t}"
                     :: "r"(a), "r"(parity) : "memory");
    }
}
__device__ __forceinline__ void ldsm4(uint& r0, uint& r1, uint& r2, uint& r3, uint a) {
    asm volatile("ldmatrix.sync.aligned.m8n8.x4.shared.b16 {%0,%1,%2,%3}, [%4];"
                 : "=r"(r0), "=r"(r1), "=r"(r2), "=r"(r3) : "r"(a));
}
__device__ __forceinline__ void mma_f16(float* c, const uint* a, uint b0, uint b1) {
    asm volatile("mma.sync.aligned.m16n8k16.row.col.f32.f16.f16.f32 "
                 "{%0,%1,%2,%3}, {%4,%5,%6,%7}, {%8,%9}, {%0,%1,%2,%3};"
                 : "+f"(c[0]), "+f"(c[1]), "+f"(c[2]), "+f"(c[3])
                 : "r"(a[0]), "r"(a[1]), "r"(a[2]), "r"(a[3]), "r"(b0), "r"(b1));
}

// ---------------- SMEM layout ----------------
#define SM_MBAR0  0
#define SM_MBAR1  16
#define SM_A0     1024
#define SM_A1     (1024 + 16384)
#define SM_B0     (1024 + 32768)
#define SM_B1     (SM_B0 + BROWS*128)      // +16896
#define SMEM_SZ   (SM_B1 + BROWS*128)      // 67584 -> 2 CTAs/SM

#define A_BYTES   16384

// ---------------- main kernel (identical to R11) ----------------
__global__ __launch_bounds__(256, 2)
void conv_hmma_fp16_kernel(float* __restrict__ out)
{
    extern __shared__ char smem[];
    const uint sb  = smem_u32(smem);
    const int tid  = threadIdx.x;
    const int wid  = tid >> 5;
    const int lid  = tid & 31;
    const int wm   = wid & 1;          // m-half (64 rows)
    const int wn   = wid >> 1;         // n-quarter (32 cols)

    const int p0  = blockIdx.x * TILE_N;
    const int oh0 = p0 / OHW;
    const int ow0 = p0 - oh0 * OHW;

    if (tid == 0) {
        mbar_init(sb + SM_MBAR0, 1);
        mbar_init(sb + SM_MBAR1, 1);
        fence_async();
    }
    __syncthreads();

    const int  rA = wm * 64 + (lid & 15);
    const int  sA = lid >> 4;
    const int  cA = rA & 7;
    const int  rB = wn * 32 + ((lid >> 4) << 3) + (lid & 7);
    const int  sB = (lid >> 3) & 1;
    int rowQ[2];
    #pragma unroll
    for (int q = 0; q < 2; ++q) {
        const int n = rB + 16 * q;
        rowQ[q] = n + ((ow0 + n >= OHW) ? 2 : 0);
    }

    auto stage_B = [&](int kr) {
        const uint bbuf = sb + ((kr & 1) ? SM_B1 : SM_B0);
        const int  qb   = (oh0 + kr) * INHW + ow0;
        #pragma unroll 1
        for (int idx = tid; idx < BROWS * 8; idx += 256) {
            const int r = idx >> 3;
            const int j = idx & 7;
            const int q = (qb + r) > QMAX ? QMAX : (qb + r);
            cpa16(bbuf + r * 128 + (((j ^ (r & 7))) << 4),
                  (const char*)g_xf + (size_t)q * 128 + j * 16);
        }
    };
    auto stage_A = [&](int t) {
        if (tid == 0) {
            const uint mb = sb + ((t & 1) ? SM_MBAR1 : SM_MBAR0);
            mbar_expect_tx(mb, A_BYTES);
            bulk_g2s(sb + ((t & 1) ? SM_A1 : SM_A0),
                     (const char*)g_wf + (size_t)t * A_BYTES, A_BYTES, mb);
        }
    };

    float acc[64];
    #pragma unroll
    for (int i = 0; i < 64; ++i) acc[i] = 0.f;

    stage_B(0); cpa_commit();
    stage_A(0);
    stage_B(1); cpa_commit();
    stage_A(1);

    int phA0 = 0, phA1 = 0;

    #pragma unroll 1
    for (int kr = 0; kr < 3; ++kr) {
        if (kr < 2) cpa_wait1();
        else        cpa_wait0();
        __syncthreads();

        const uint bbuf = sb + ((kr & 1) ? SM_B1 : SM_B0);

        #pragma unroll 1
        for (int ks = 0; ks < 3; ++ks) {
            const int t = kr * 3 + ks;
            const int b = t & 1;
            if (b == 0) { mbar_wait(sb + SM_MBAR0, phA0); phA0 ^= 1; }
            else        { mbar_wait(sb + SM_MBAR1, phA1); phA1 ^= 1; }

            const uint abuf = sb + (b ? SM_A1 : SM_A0);
            const uint aRow = abuf + (uint)rA * 128;

            #pragma unroll
            for (int k = 0; k < 4; ++k) {
                uint bf[8];
                #pragma unroll
                for (int q = 0; q < 2; ++q) {
                    const int  row  = rowQ[q] + ks;
                    const uint addr = bbuf + (uint)row * 128
                                    + (uint)(((2 * k + sB) ^ (row & 7)) << 4);
                    ldsm4(bf[q*4+0], bf[q*4+1], bf[q*4+2], bf[q*4+3], addr);
                }
                #pragma unroll
                for (int i = 0; i < 4; ++i) {
                    uint a[4];
                    ldsm4(a[0], a[1], a[2], a[3],
                          aRow + (uint)i * 2048 + (uint)(((2 * k + sA) ^ cA) << 4));
                    #pragma unroll
                    for (int j = 0; j < 4; ++j)
                        mma_f16(&acc[(i * 4 + j) * 4], a, bf[j*2], bf[j*2+1]);
                }
            }
            __syncthreads();
            if (t + 2 <= 8) stage_A(t + 2);
        }
        if (kr == 0) { stage_B(2); cpa_commit(); }
    }

    const int ml = wm * 64 + (lid >> 2);
    const int nl = wn * 32 + (lid & 3) * 2;
    #pragma unroll
    for (int i = 0; i < 4; ++i) {
        #pragma unroll
        for (int j = 0; j < 4; ++j) {
            const float* c = &acc[(i * 4 + j) * 4];
            const int n = nl + j * 8;
            const int p = p0 + n;
            if (p < NPIX) {
                const int m0 = ml + i * 16;
                *(float2*)(out + (size_t)m0 * NPIX + p)       = make_float2(c[0], c[1]);
                *(float2*)(out + (size_t)(m0 + 8) * NPIX + p) = make_float2(c[2], c[3]);
            }
        }
    }
}

// ---------------- launch ----------------
extern "C" void kernel_launch(void* const* d_in, const int* in_sizes, int n_in,
                              void* d_out, int out_size)
{
    const float* x = (const float*)d_in[0];   // (64, 224, 224) f32
    const float* w = (const float*)d_in[1];   // (128, 64, 3, 3) f32
    float* out = (float*)d_out;               // (128, 222, 222) f32

    cudaFuncSetAttribute(conv_hmma_fp16_kernel,
                         cudaFuncAttributeMaxDynamicSharedMemorySize, SMEM_SZ);

    prep_kernel<<<XBLK + WBLK, 256>>>(x, w);
    conv_hmma_fp16_kernel<<<NTILES, 256, SMEM_SZ>>>(out);
}

// round 13
// speedup vs baseline: 3.5968x; 1.0256x over previous
#include <cuda_runtime.h>
#include <cuda_fp16.h>
#include <cstdint>

typedef unsigned int uint;

#define C_IN    64
#define INHW    224
#define NQ      (INHW*INHW)        // 50176 input pixels
#define QMAX    (NQ-1)
#define C_OUT   128
#define OHW     222
#define NPIX    (OHW*OHW)          // 49284
#define NTAP    9
#define TILE_N  128
#define NTILES  ((NPIX + TILE_N - 1)/TILE_N)   // 386
#define BROWS   132                // B smem rows per kr (128 + ks 2 + rowcross 2)

#define XBLK    (NQ/256)           // 196 transpose blocks
#define WBLK    36                 // 36 blocks x 2048 items = 73728 weight elems

// x transposed to [q][ic] fp16 (6.4 MB)
__device__ __align__(16) __half g_xf[NQ * C_IN];
// w as [tap][oc][ic] fp16 with XOR-swizzle pre-baked per oc row (verbatim bulk copy)
__device__ __align__(16) __half g_wf[NTAP * C_OUT * C_IN];

// ---------------- combined prep kernel (unchanged from R12) ----------------
__global__ void prep_kernel(const float* __restrict__ x, const float* __restrict__ w)
{
    const int tid = threadIdx.x;
    if (blockIdx.x < XBLK) {
        __shared__ __half sm[256 * 64];          // 32 KB
        const int q0 = blockIdx.x * 256;
        #pragma unroll 8
        for (int c = 0; c < 64; ++c) {
            float v = x[(size_t)c * NQ + q0 + tid];
            sm[tid * 64 + (((c >> 3) ^ (tid & 7)) << 3) + (c & 7)] = __float2half(v);
        }
        __syncthreads();
        #pragma unroll
        for (int it = 0; it < 8; ++it) {
            const int i = tid + it * 256;
            const int q = i >> 3;
            const int g = i & 7;
            uint4 v = *(const uint4*)&sm[q * 64 + ((g ^ (q & 7)) << 3)];
            *(uint4*)&g_xf[(size_t)(q0 + q) * 64 + g * 8] = v;
        }
    } else {
        const int base = (blockIdx.x - XBLK) * 2048 + tid * 8;
        #pragma unroll
        for (int k = 0; k < 8; ++k) {
            const int i = base + k;
            if (i < NTAP * C_OUT * C_IN) {
                const int ic = i & 63;
                const int r  = i >> 6;
                const int oc = r & 127;
                const int t  = r >> 7;
                float v = w[(size_t)(oc * C_IN + ic) * NTAP + t];
                const int jp = (ic >> 3) ^ (oc & 7);
                g_wf[(size_t)t * (C_OUT * C_IN) + oc * C_IN + jp * 8 + (ic & 7)] =
                    __float2half(v);
            }
        }
    }
}

// ---------------- PTX helpers ----------------
__device__ __forceinline__ uint smem_u32(const void* p) {
    uint a;
    asm("{ .reg .u64 t; cvta.to.shared.u64 t, %1; cvt.u32.u64 %0, t; }"
        : "=r"(a) : "l"(p));
    return a;
}
__device__ __forceinline__ void cpa16(uint d, const void* s) {
    asm volatile("cp.async.ca.shared.global [%0], [%1], 16;" :: "r"(d), "l"(s) : "memory");
}
__device__ __forceinline__ void cpa_commit() {
    asm volatile("cp.async.commit_group;" ::: "memory");
}
__device__ __forceinline__ void cpa_wait2() {
    asm volatile("cp.async.wait_group 2;" ::: "memory");
}
__device__ __forceinline__ void cpa_wait1() {
    asm volatile("cp.async.wait_group 1;" ::: "memory");
}
__device__ __forceinline__ void cpa_wait0() {
    asm volatile("cp.async.wait_group 0;" ::: "memory");
}
__device__ __forceinline__ void mbar_init(uint a, uint cnt) {
    asm volatile("mbarrier.init.shared.b64 [%0], %1;" :: "r"(a), "r"(cnt) : "memory");
}
__device__ __forceinline__ void mbar_expect_tx(uint a, uint bytes) {
    asm volatile("mbarrier.arrive.expect_tx.shared.b64 _, [%0], %1;"
                 :: "r"(a), "r"(bytes) : "memory");
}
__device__ __forceinline__ void bulk_g2s(uint dst, const void* src, uint bytes, uint mbar) {
    asm volatile("cp.async.bulk.shared::cluster.global.mbarrier::complete_tx::bytes "
                 "[%0], [%1], %2, [%3];"
                 :: "r"(dst), "l"(src), "r"(bytes), "r"(mbar) : "memory");
}
__device__ __forceinline__ void fence_async() {
    asm volatile("fence.proxy.async.shared::cta;" ::: "memory");
}
__device__ __forceinline__ void mbar_wait(uint a, uint parity) {
    uint done;
    asm volatile("{\n\t.reg .pred p;\n\t"
                 "mbarrier.try_wait.parity.acquire.cta.shared::cta.b64 p, [%1], %2;\n\t"
                 "selp.b32 %0, 1, 0, p;\n\t}"
                 : "=r"(done) : "r"(a), "r"(parity) : "memory");
    if (!done) {
        asm volatile("{\n\t.reg .pred P1;\n\t"
                     "WL_%=:\n\t"
                     "mbarrier.try_wait.parity.acquire.cta.shared::cta.b64 P1, [%0], %1, 0x989680;\n\t"
                     "@P1 bra.uni WD_%=;\n\t"
                     "bra.uni WL_%=;\n\t"
                     "WD_%=:\n\t}"
                     :: "r"(a), "r"(parity) : "memory");
    }
}
__device__ __forceinline__ void ldsm4(uint& r0, uint& r1, uint& r2, uint& r3, uint a) {
    asm volatile("ldmatrix.sync.aligned.m8n8.x4.shared.b16 {%0,%1,%2,%3}, [%4];"
                 : "=r"(r0), "=r"(r1), "=r"(r2), "=r"(r3) : "r"(a));
}
__device__ __forceinline__ void mma_f16(float* c, const uint* a, uint b0, uint b1) {
    asm volatile("mma.sync.aligned.m16n8k16.row.col.f32.f16.f16.f32 "
                 "{%0,%1,%2,%3}, {%4,%5,%6,%7}, {%8,%9}, {%0,%1,%2,%3};"
                 : "+f"(c[0]), "+f"(c[1]), "+f"(c[2]), "+f"(c[3])
                 : "r"(a[0]), "r"(a[1]), "r"(a[2]), "r"(a[3]), "r"(b0), "r"(b1));
}

// ---------------- SMEM layout: 3x A bufs, 3x B bufs ----------------
#define SM_MBAR   0                 // 3 mbarriers (A bufs), 16B apart
#define SM_A0     1024
#define A_BYTES   16384
#define SM_B0     (1024 + 3*A_BYTES)       // 50176
#define B_BYTES   (BROWS*128)              // 16896
#define SMEM_SZ   (SM_B0 + 3*B_BYTES)      // 100864 -> 2 CTAs/SM

// ---------------- main kernel ----------------
__global__ __launch_bounds__(256, 2)
void conv_hmma_fp16_kernel(float* __restrict__ out)
{
    extern __shared__ char smem[];
    const uint sb  = smem_u32(smem);
    const int tid  = threadIdx.x;
    const int wid  = tid >> 5;
    const int lid  = tid & 31;
    const int wm   = wid & 1;          // m-half (64 rows)
    const int wn   = wid >> 1;         // n-quarter (32 cols)

    const int p0  = blockIdx.x * TILE_N;
    const int oh0 = p0 / OHW;
    const int ow0 = p0 - oh0 * OHW;

    if (tid == 0) {
        mbar_init(sb + SM_MBAR +  0, 1);
        mbar_init(sb + SM_MBAR + 16, 1);
        mbar_init(sb + SM_MBAR + 32, 1);
        fence_async();
    }
    __syncthreads();

    const int  rA = wm * 64 + (lid & 15);
    const int  sA = lid >> 4;
    const int  cA = rA & 7;
    const int  rB = wn * 32 + ((lid >> 4) << 3) + (lid & 7);
    const int  sB = (lid >> 3) & 1;
    int rowQ[2];
    #pragma unroll
    for (int q = 0; q < 2; ++q) {
        const int n = rB + 16 * q;
        rowQ[q] = n + ((ow0 + n >= OHW) ? 2 : 0);
    }

    // ---- B staging (LDGSTS) into buf kr; all three issued in the prologue ----
    auto stage_B = [&](int kr) {
        const uint bbuf = sb + SM_B0 + (uint)kr * B_BYTES;
        const int  qb   = (oh0 + kr) * INHW + ow0;
        #pragma unroll 1
        for (int idx = tid; idx < BROWS * 8; idx += 256) {
            const int r = idx >> 3;
            const int j = idx & 7;
            const int q = (qb + r) > QMAX ? QMAX : (qb + r);
            cpa16(bbuf + r * 128 + (((j ^ (r & 7))) << 4),
                  (const char*)g_xf + (size_t)q * 128 + j * 16);
        }
    };
    // ---- A staging (one bulk per tap) into buf t%3 ----
    auto stage_A = [&](int t) {
        if (tid == 0) {
            const int  b  = t % 3;
            const uint mb = sb + SM_MBAR + (uint)b * 16;
            mbar_expect_tx(mb, A_BYTES);
            bulk_g2s(sb + SM_A0 + (uint)b * A_BYTES,
                     (const char*)g_wf + (size_t)t * A_BYTES, A_BYTES, mb);
        }
    };

    float acc[64];
    #pragma unroll
    for (int i = 0; i < 64; ++i) acc[i] = 0.f;

    // prologue: all B slabs + first two A taps in flight
    stage_B(0); cpa_commit();
    stage_B(1); cpa_commit();
    stage_B(2); cpa_commit();
    stage_A(0);
    stage_A(1);

    #pragma unroll 1
    for (int t = 0; t < NTAP; ++t) {
        const int kr = t / 3;
        if      (t == 0) cpa_wait2();       // B(0) landed
        else if (t == 3) cpa_wait1();       // B(1) landed
        else if (t == 6) cpa_wait0();       // B(2) landed

        const int b = t % 3;
        mbar_wait(sb + SM_MBAR + (uint)b * 16, (t / 3) & 1);   // A(t) landed
        __syncthreads();                    // gates: data visible to all warps AND
                                            // all warps finished tap t-1's buffers
        if (t + 2 < NTAP) stage_A(t + 2);   // refill buf (t+2)%3, consumed at tap t-1

        const uint abuf = sb + SM_A0 + (uint)b * A_BYTES;
        const uint bbuf = sb + SM_B0 + (uint)kr * B_BYTES;
        const uint aRow = abuf + (uint)rA * 128;
        const int  ks   = t - kr * 3;

        #pragma unroll
        for (int k = 0; k < 4; ++k) {
            uint bf[8];
            #pragma unroll
            for (int q = 0; q < 2; ++q) {
                const int  row  = rowQ[q] + ks;
                const uint addr = bbuf + (uint)row * 128
                                + (uint)(((2 * k + sB) ^ (row & 7)) << 4);
                ldsm4(bf[q*4+0], bf[q*4+1], bf[q*4+2], bf[q*4+3], addr);
            }
            #pragma unroll
            for (int i = 0; i < 4; ++i) {
                uint a[4];
                ldsm4(a[0], a[1], a[2], a[3],
                      aRow + (uint)i * 2048 + (uint)(((2 * k + sA) ^ cA) << 4));
                #pragma unroll
                for (int j = 0; j < 4; ++j)
                    mma_f16(&acc[(i * 4 + j) * 4], a, bf[j*2], bf[j*2+1]);
            }
        }
        // no trailing barrier: next tap's top __syncthreads fences buffer reuse
    }

    // ---- epilogue (unchanged) ----
    const int ml = wm * 64 + (lid >> 2);
    const int nl = wn * 32 + (lid & 3) * 2;
    #pragma unroll
    for (int i = 0; i < 4; ++i) {
        #pragma unroll
        for (int j = 0; j < 4; ++j) {
            const float* c = &acc[(i * 4 + j) * 4];
            const int n = nl + j * 8;
            const int p = p0 + n;
            if (p < NPIX) {
                const int m0 = ml + i * 16;
                *(float2*)(out + (size_t)m0 * NPIX + p)       = make_float2(c[0], c[1]);
                *(float2*)(out + (size_t)(m0 + 8) * NPIX + p) = make_float2(c[2], c[3]);
            }
        }
    }
}

// ---------------- launch ----------------
extern "C" void kernel_launch(void* const* d_in, const int* in_sizes, int n_in,
                              void* d_out, int out_size)
{
    const float* x = (const float*)d_in[0];   // (64, 224, 224) f32
    const float* w = (const float*)d_in[1];   // (128, 64, 3, 3) f32
    float* out = (float*)d_out;               // (128, 222, 222) f32

    cudaFuncSetAttribute(conv_hmma_fp16_kernel,
                         cudaFuncAttributeMaxDynamicSharedMemorySize, SMEM_SZ);

    prep_kernel<<<XBLK + WBLK, 256>>>(x, w);
    conv_hmma_fp16_kernel<<<NTILES, 256, SMEM_SZ>>>(out);
}